// round 13
// baseline (speedup 1.0000x reference)
#include <cuda_runtime.h>
#include <cuda_bf16.h>
#include <cuda_pipeline.h>
#include <mma.h>
#include <math.h>
#include <stdint.h>

using namespace nvcuda;

#define NPTS 8192
#define DIN  512
#define HID  1024
#define EMBD 64
#define NEFF 2
#define NCONS 62   // EMBD - NEFF
#define NCLS 16
#define MARGIN 0.01f

// ---------------- scratch (static device globals; no allocation) ----------------
__device__ __nv_bfloat16 g_xhi[NPTS * DIN],  g_xlo[NPTS * DIN];
__device__ __nv_bfloat16 g_w1hi[DIN * HID],  g_w1lo[DIN * HID];
__device__ __nv_bfloat16 g_w2hi[HID * EMBD], g_w2lo[HID * EMBD];
__device__ __nv_bfloat16 g_w3hi[EMBD * HID], g_w3lo[EMBD * HID];
__device__ __nv_bfloat16 g_w4hi[HID * DIN],  g_w4lo[HID * DIN];
__device__ __nv_bfloat16 g_h1hi[NPTS * HID], g_h1lo[NPTS * HID];
__device__ __nv_bfloat16 g_h2hi[NPTS * HID], g_h2lo[NPTS * HID];
__device__ __nv_bfloat16 g_ehi[NPTS * EMBD], g_elo[NPTS * EMBD];
__device__ float g_emb[NPTS * EMBD];
__device__ float g_sq[NPTS];
__device__ int   g_lbl[NPTS];
__device__ int   g_cnt[NCLS];
__device__ int   g_off[NCLS + 1];
__device__ int   g_cur[NCLS];
__device__ int   g_perm[NPTS];
__device__ int   g_tileoff[NCLS + 1];
__device__ float g_msum[NCLS * NCONS];
__device__ float g_T[NCLS];
__device__ float g_cdiff;

__device__ __forceinline__ uint32_t pack_bf2(__nv_bfloat16 a, __nv_bfloat16 b) {
    __nv_bfloat162 t = __halves2bfloat162(a, b);
    return *reinterpret_cast<uint32_t*>(&t);
}

// ---------------- split x (+ fused init of per-launch accumulators) ----------------
__global__ void split_x_init_kernel(const float* __restrict__ x) {
    if (blockIdx.x == 0) {                        // fused init (cheap, once)
        int t = threadIdx.x;
        for (int i = t; i < NCLS * NCONS; i += 256) g_msum[i] = 0.f;
        if (t < NCLS) { g_T[t] = 0.f; g_cnt[t] = 0; g_cur[t] = 0; }
        if (t == 0) g_cdiff = 0.f;
    }
    // 4 elems per thread; NPTS*DIN/1024 blocks, exact
    int q = blockIdx.x * 256 + threadIdx.x;       // quad index
    int r = q / (DIN / 4), c = (q % (DIN / 4)) * 4;
    const float* xp = x + (long)r * (DIN + 1) + 1 + c;
    float v0 = xp[0], v1 = xp[1], v2 = xp[2], v3 = xp[3];
    __nv_bfloat16 h0 = __float2bfloat16(v0), h1 = __float2bfloat16(v1);
    __nv_bfloat16 h2 = __float2bfloat16(v2), h3 = __float2bfloat16(v3);
    uint2 uh, ul;
    uh.x = pack_bf2(h0, h1); uh.y = pack_bf2(h2, h3);
    ul.x = pack_bf2(__float2bfloat16(v0 - __bfloat162float(h0)),
                    __float2bfloat16(v1 - __bfloat162float(h1)));
    ul.y = pack_bf2(__float2bfloat16(v2 - __bfloat162float(h2)),
                    __float2bfloat16(v3 - __bfloat162float(h3)));
    *(uint2*)&g_xhi[q * 4] = uh;
    *(uint2*)&g_xlo[q * 4] = ul;
}

// ---------------- merged, vectorized weight split (all 4 weights, one launch) ----------------
#define W1N (DIN * HID)
#define W2N (HID * EMBD)
#define W3N (EMBD * HID)
#define W4N (HID * DIN)
#define WTOT (W1N + W2N + W3N + W4N)

__global__ void split_w_all_kernel(const float* __restrict__ W1, const float* __restrict__ W2,
                                   const float* __restrict__ W3, const float* __restrict__ W4) {
    int q = blockIdx.x * 256 + threadIdx.x;       // quad index; WTOT/1024 blocks, exact
    int idx = q * 4;
    const float* src;
    __nv_bfloat16 *hi, *lo;
    int off;
    if (idx < W1N)                    { src = W1; hi = g_w1hi; lo = g_w1lo; off = idx; }
    else if (idx < W1N + W2N)         { src = W2; hi = g_w2hi; lo = g_w2lo; off = idx - W1N; }
    else if (idx < W1N + W2N + W3N)   { src = W3; hi = g_w3hi; lo = g_w3lo; off = idx - W1N - W2N; }
    else                              { src = W4; hi = g_w4hi; lo = g_w4lo; off = idx - W1N - W2N - W3N; }
    float4 v = *(const float4*)&src[off];
    __nv_bfloat16 h0 = __float2bfloat16(v.x), h1 = __float2bfloat16(v.y);
    __nv_bfloat16 h2 = __float2bfloat16(v.z), h3 = __float2bfloat16(v.w);
    uint2 uh, ul;
    uh.x = pack_bf2(h0, h1); uh.y = pack_bf2(h2, h3);
    ul.x = pack_bf2(__float2bfloat16(v.x - __bfloat162float(h0)),
                    __float2bfloat16(v.y - __bfloat162float(h1)));
    ul.y = pack_bf2(__float2bfloat16(v.z - __bfloat162float(h2)),
                    __float2bfloat16(v.w - __bfloat162float(h3)));
    *(uint2*)&hi[off] = uh;
    *(uint2*)&lo[off] = ul;
}

// ================= WMMA bf16 split GEMM, cp.async 2-stage pipeline (R11-proven core) =================
// OUTMODE: 0 = fp32 only, 1 = split bf16 only, 2 = both.
template<int BM, int BN, int WM, int WN, int OUTMODE, bool DOTANH>
__global__ __launch_bounds__(256, 2)
void hgemm_cp(const __nv_bfloat16* __restrict__ Ahi_g, const __nv_bfloat16* __restrict__ Alo_g,
              const __nv_bfloat16* __restrict__ Bhi_g, const __nv_bfloat16* __restrict__ Blo_g,
              const float* __restrict__ bias,
              float* __restrict__ C, __nv_bfloat16* __restrict__ Chi,
              __nv_bfloat16* __restrict__ Clo, int K, int N)
{
    constexpr int BK = 32, BKP = 40, BNP = BN + 8;
    constexpr int MW = BM / WM, NW = BN / WN;
    static_assert(MW * NW == 8, "8 warps");
    constexpr int MFRAG = WM / 16, NFRAG = WN / 16;
    constexpr int A_EL = BM * BKP;                 // bf16 elems per A buffer
    constexpr int B_EL = BK * BNP;
    constexpr int STAGE_EL = 2 * A_EL + 2 * B_EL;  // hi+lo for A and B

    extern __shared__ __align__(16) unsigned char dsm[];
    __nv_bfloat16* sbase = (__nv_bfloat16*)dsm;
    float* stage_epi = (float*)dsm;                // overlays tiles (dead in epilogue)

    const int tid = threadIdx.x;
    const int wid = tid >> 5, lid = tid & 31;
    const int wm = wid % MW, wn = wid / MW;
    const int rowBase = blockIdx.y * BM;
    const int n0 = blockIdx.x * BN;

    auto AhiS = [&](int s) { return sbase + s * STAGE_EL; };
    auto AloS = [&](int s) { return sbase + s * STAGE_EL + A_EL; };
    auto BhiS = [&](int s) { return sbase + s * STAGE_EL + 2 * A_EL; };
    auto BloS = [&](int s) { return sbase + s * STAGE_EL + 2 * A_EL + B_EL; };

    // async stage loader: pure 16B copies (warp-uniform control flow)
    auto load_stage = [&](int s, int ch) {
        const int k0 = ch * BK;
        __nv_bfloat16* ah = AhiS(s);
        __nv_bfloat16* al = AloS(s);
        __nv_bfloat16* bh = BhiS(s);
        __nv_bfloat16* bl = BloS(s);
        constexpr int AU = BM * BK / 8;            // uint4 count per A buffer
#pragma unroll
        for (int i = tid; i < AU; i += 256) {
            int r = i >> 2, c8 = (i & 3) << 3;
            long src = (long)(rowBase + r) * K + k0 + c8;
            int dst = r * BKP + c8;
            __pipeline_memcpy_async(&ah[dst], &Ahi_g[src], 16);
            __pipeline_memcpy_async(&al[dst], &Alo_g[src], 16);
        }
        constexpr int BU = BK * BN / 8;
        constexpr int BROW = BN / 8;
#pragma unroll
        for (int i = tid; i < BU; i += 256) {
            int r = i / BROW, c8 = (i % BROW) << 3;
            long src = (long)(k0 + r) * N + n0 + c8;
            int dst = r * BNP + c8;
            __pipeline_memcpy_async(&bh[dst], &Bhi_g[src], 16);
            __pipeline_memcpy_async(&bl[dst], &Blo_g[src], 16);
        }
        __pipeline_commit();
    };

    wmma::fragment<wmma::accumulator, 16, 16, 16, float> acc[MFRAG][NFRAG];
#pragma unroll
    for (int mf = 0; mf < MFRAG; mf++)
#pragma unroll
        for (int nf = 0; nf < NFRAG; nf++)
            wmma::fill_fragment(acc[mf][nf], 0.0f);

    const int nChunks = K / BK;
    load_stage(0, 0);

    for (int ch = 0; ch < nChunks; ch++) {
        const int buf = ch & 1;
        if (ch + 1 < nChunks) {
            load_stage(buf ^ 1, ch + 1);
            __pipeline_wait_prior(1);              // stage ch complete
        } else {
            __pipeline_wait_prior(0);
        }
        __syncthreads();

        const __nv_bfloat16* Ahi = AhiS(buf);
        const __nv_bfloat16* Alo = AloS(buf);
        const __nv_bfloat16* Bhi = BhiS(buf);
        const __nv_bfloat16* Blo = BloS(buf);

#pragma unroll
        for (int kf = 0; kf < BK / 16; kf++) {
            wmma::fragment<wmma::matrix_a, 16, 16, 16, __nv_bfloat16, wmma::row_major> ah[MFRAG], al[MFRAG];
#pragma unroll
            for (int mf = 0; mf < MFRAG; mf++) {
                wmma::load_matrix_sync(ah[mf], &Ahi[(wm * WM + mf * 16) * BKP + kf * 16], BKP);
                wmma::load_matrix_sync(al[mf], &Alo[(wm * WM + mf * 16) * BKP + kf * 16], BKP);
            }
#pragma unroll
            for (int nf = 0; nf < NFRAG; nf++) {
                wmma::fragment<wmma::matrix_b, 16, 16, 16, __nv_bfloat16, wmma::row_major> bh, bl;
                wmma::load_matrix_sync(bh, &Bhi[(kf * 16) * BNP + wn * WN + nf * 16], BNP);
                wmma::load_matrix_sync(bl, &Blo[(kf * 16) * BNP + wn * WN + nf * 16], BNP);
#pragma unroll
                for (int mf = 0; mf < MFRAG; mf++) {
                    wmma::mma_sync(acc[mf][nf], ah[mf], bh, acc[mf][nf]);
                    wmma::mma_sync(acc[mf][nf], al[mf], bh, acc[mf][nf]);
                    wmma::mma_sync(acc[mf][nf], ah[mf], bl, acc[mf][nf]);
                }
            }
        }
        __syncthreads();   // all reads of buf done before next iteration's load overwrites it
    }

    // ---- epilogue via per-warp smem staging ----
    float* wstage = stage_epi + wid * (16 * 20);
#pragma unroll
    for (int mf = 0; mf < MFRAG; mf++) {
#pragma unroll
        for (int nf = 0; nf < NFRAG; nf++) {
            wmma::store_matrix_sync(wstage, acc[mf][nf], 20, wmma::mem_row_major);
            __syncwarp();
            int r = lid >> 1, c0 = (lid & 1) << 3;
            long grow = rowBase + wm * WM + mf * 16 + r;
            int gcol = n0 + wn * WN + nf * 16 + c0;
            const float4* bp = (const float4*)&bias[gcol];
            float4 b0 = bp[0], b1 = bp[1];
            float v[8];
            v[0] = wstage[r * 20 + c0 + 0] + b0.x;
            v[1] = wstage[r * 20 + c0 + 1] + b0.y;
            v[2] = wstage[r * 20 + c0 + 2] + b0.z;
            v[3] = wstage[r * 20 + c0 + 3] + b0.w;
            v[4] = wstage[r * 20 + c0 + 4] + b1.x;
            v[5] = wstage[r * 20 + c0 + 5] + b1.y;
            v[6] = wstage[r * 20 + c0 + 6] + b1.z;
            v[7] = wstage[r * 20 + c0 + 7] + b1.w;
            if (DOTANH) {
#pragma unroll
                for (int j = 0; j < 8; j++) v[j] = tanhf(v[j]);
            }
            if (OUTMODE != 1) {
                float4* cp = (float4*)&C[grow * N + gcol];
                cp[0] = make_float4(v[0], v[1], v[2], v[3]);
                cp[1] = make_float4(v[4], v[5], v[6], v[7]);
            }
            if (OUTMODE >= 1) {
                __nv_bfloat16 h[8];
                uint4 uh, ul;
#pragma unroll
                for (int j = 0; j < 8; j++) h[j] = __float2bfloat16(v[j]);
                uh.x = pack_bf2(h[0], h[1]); uh.y = pack_bf2(h[2], h[3]);
                uh.z = pack_bf2(h[4], h[5]); uh.w = pack_bf2(h[6], h[7]);
                __nv_bfloat16 l[8];
#pragma unroll
                for (int j = 0; j < 8; j++)
                    l[j] = __float2bfloat16(v[j] - __bfloat162float(h[j]));
                ul.x = pack_bf2(l[0], l[1]); ul.y = pack_bf2(l[2], l[3]);
                ul.z = pack_bf2(l[4], l[5]); ul.w = pack_bf2(l[6], l[7]);
                *(uint4*)&Chi[grow * N + gcol] = uh;
                *(uint4*)&Clo[grow * N + gcol] = ul;
            }
            __syncwarp();
        }
    }
}

// ---------------- per-point / per-class statistics ----------------
__global__ void stats_kernel(const float* __restrict__ x) {
    __shared__ float sm[NCLS * NCONS];
    __shared__ float sT[NCLS];
    __shared__ int   sC[NCLS];
    int tid = threadIdx.x;
    for (int i = tid; i < NCLS * NCONS; i += blockDim.x) sm[i] = 0.f;
    if (tid < NCLS) { sT[tid] = 0.f; sC[tid] = 0; }
    __syncthreads();

    int i = blockIdx.x * blockDim.x + tid;       // exact coverage (32*256 = 8192)
    int l = (int)x[(long)i * (DIN + 1)];
    const float* e = g_emb + (long)i * EMBD + NEFF;
    float sq = 0.f;
#pragma unroll
    for (int d = 0; d < NCONS; d++) {
        float v = e[d];
        sq += v * v;
        atomicAdd(&sm[l * NCONS + d], v);
    }
    g_sq[i] = sq;
    g_lbl[i] = l;
    atomicAdd(&sT[l], sq);
    atomicAdd(&sC[l], 1);
    __syncthreads();

    for (int j = tid; j < NCLS * NCONS; j += blockDim.x) atomicAdd(&g_msum[j], sm[j]);
    if (tid < NCLS) {
        atomicAdd(&g_T[tid], sT[tid]);
        atomicAdd(&g_cnt[tid], sC[tid]);
    }
}

// ---------------- counting-sort offsets + tile offsets ----------------
__global__ void offsets_kernel() {
    if (threadIdx.x == 0 && blockIdx.x == 0) {
        int acc = 0, tacc = 0;
        for (int k = 0; k < NCLS; k++) {
            g_off[k] = acc; acc += g_cnt[k];
            g_cur[k] = 0;
            int t = (g_cnt[k] + 31) >> 5;
            g_tileoff[k] = tacc; tacc += t * t;
        }
        g_off[NCLS] = acc;
        g_tileoff[NCLS] = tacc;
    }
}

__global__ void scatter_kernel() {
    int i = blockIdx.x * blockDim.x + threadIdx.x;
    int l = g_lbl[i];
    int pos = g_off[l] + atomicAdd(&g_cur[l], 1);
    g_perm[pos] = i;
}

// ---------------- same-class pairwise C_diff (persistent tile loop) ----------------
__global__ __launch_bounds__(256)
void pairwise_kernel() {
    __shared__ float Ci[32][NCONS + 1];   // pad to 63: conflict-free
    __shared__ float Cj[32][NCONS + 1];
    __shared__ float sqi[32], sqj[32];
    __shared__ float red[256];

    int tid = threadIdx.x;
    int total = g_tileoff[NCLS];
    float accT = 0.f;

    for (int w = blockIdx.x; w < total; w += gridDim.x) {
        int k = 0;
        while (g_tileoff[k + 1] <= w) k++;
        int n = g_cnt[k];
        int tpd = (n + 31) >> 5;
        int local = w - g_tileoff[k];
        int ti = local / tpd, tj = local % tpd;
        int base = g_off[k];
        int ni = min(32, n - ti * 32);
        int nj = min(32, n - tj * 32);

        __syncthreads();   // protect shared reuse across tiles
        for (int idx = tid; idx < 32 * NCONS; idx += blockDim.x) {
            int r = idx / NCONS, d = idx % NCONS;
            int a = ti * 32 + r;
            if (a < n) {
                int gi = g_perm[base + a];
                Ci[r][d] = g_emb[(long)gi * EMBD + NEFF + d];
                if (d == 0) sqi[r] = g_sq[gi];
            }
            int b = tj * 32 + r;
            if (b < n) {
                int gj = g_perm[base + b];
                Cj[r][d] = g_emb[(long)gj * EMBD + NEFF + d];
                if (d == 0) sqj[r] = g_sq[gj];
            }
        }
        __syncthreads();

        int b = tid & 31;        // varies across warp -> conflict-free Cj reads
        int a0 = tid >> 5;       // uniform across warp -> broadcast Ci reads
        if (b < nj) {
            float dot0 = 0.f, dot1 = 0.f, dot2 = 0.f, dot3 = 0.f;
#pragma unroll
            for (int d = 0; d < NCONS; d++) {
                float cj = Cj[b][d];
                dot0 += Ci[a0][d] * cj;
                dot1 += Ci[a0 + 8][d] * cj;
                dot2 += Ci[a0 + 16][d] * cj;
                dot3 += Ci[a0 + 24][d] * cj;
            }
            float sj = sqj[b];
            float dots[4] = {dot0, dot1, dot2, dot3};
#pragma unroll
            for (int m = 0; m < 4; m++) {
                int a = a0 + m * 8;
                if (a < ni) {
                    float D = fmaxf(sqi[a] + sj - 2.f * dots[m], 0.f) * (1.f / NCONS);
                    float t = MARGIN - D;
                    if (t > 0.f) accT += t;
                }
            }
        }
    }

    red[tid] = accT;
    __syncthreads();
    for (int s = 128; s > 0; s >>= 1) {
        if (tid < s) red[tid] += red[tid + s];
        __syncthreads();
    }
    if (tid == 0 && red[0] != 0.f) atomicAdd(&g_cdiff, red[0]);
}

// ---------------- finalize: parallel closed-form C_sim, normalize C_diff ----------------
__global__ void finalize_kernel(float* __restrict__ out) {
    __shared__ float Msh[NCONS];
    __shared__ float s_summ2, s_sumTw, s_MM;
    __shared__ unsigned long long s_n2;
    int tid = threadIdx.x;
    if (tid < NCONS) Msh[tid] = 0.f;
    if (tid == 0) { s_summ2 = 0.f; s_sumTw = 0.f; s_MM = 0.f; s_n2 = 0ull; }
    __syncthreads();

    float p2 = 0.f;
    for (int i = tid; i < NCLS * NCONS; i += blockDim.x) {
        float v = g_msum[i];
        p2 += v * v;
        atomicAdd(&Msh[i % NCONS], v);
    }
    if (p2 != 0.f) atomicAdd(&s_summ2, p2);
    if (tid < NCLS) {
        int n = g_cnt[tid];
        atomicAdd(&s_n2, (unsigned long long)n * (unsigned long long)n);
        atomicAdd(&s_sumTw, g_T[tid] * (float)(NPTS - n));
    }
    __syncthreads();
    if (tid < NCONS) atomicAdd(&s_MM, Msh[tid] * Msh[tid]);
    __syncthreads();

    if (tid == 0) {
        double ndiff = (double)NPTS * (double)NPTS - (double)s_n2;
        float raw = 2.f * s_sumTw - 2.f * (s_MM - s_summ2);
        float csim = raw * (1.f / NCONS) / (float)(ndiff + 1.0);
        float cdiff = g_cdiff / (float)((double)NPTS * (double)NPTS - ndiff + 1.0);
        out[(long)NPTS * DIN]     = csim;
        out[(long)NPTS * DIN + 1] = cdiff;
    }
}

// ---------------- launch ----------------
extern "C" void kernel_launch(void* const* d_in, const int* in_sizes, int n_in,
                              void* d_out, int out_size) {
    const float* x  = (const float*)d_in[0];
    const float* W1 = (const float*)d_in[1];
    const float* b1 = (const float*)d_in[2];
    const float* W2 = (const float*)d_in[3];
    const float* b2 = (const float*)d_in[4];
    const float* W3 = (const float*)d_in[5];
    const float* b3 = (const float*)d_in[6];
    const float* W4 = (const float*)d_in[7];
    const float* b4 = (const float*)d_in[8];
    float* out = (float*)d_out;

    void *pxh, *pxl, *p1h, *p1l, *p2h, *p2l, *p3h, *p3l, *p4h, *p4l;
    void *ph1h, *ph1l, *ph2h, *ph2l, *peh, *pel, *pemb;
    cudaGetSymbolAddress(&pxh, g_xhi);   cudaGetSymbolAddress(&pxl, g_xlo);
    cudaGetSymbolAddress(&p1h, g_w1hi);  cudaGetSymbolAddress(&p1l, g_w1lo);
    cudaGetSymbolAddress(&p2h, g_w2hi);  cudaGetSymbolAddress(&p2l, g_w2lo);
    cudaGetSymbolAddress(&p3h, g_w3hi);  cudaGetSymbolAddress(&p3l, g_w3lo);
    cudaGetSymbolAddress(&p4h, g_w4hi);  cudaGetSymbolAddress(&p4l, g_w4lo);
    cudaGetSymbolAddress(&ph1h, g_h1hi); cudaGetSymbolAddress(&ph1l, g_h1lo);
    cudaGetSymbolAddress(&ph2h, g_h2hi); cudaGetSymbolAddress(&ph2l, g_h2lo);
    cudaGetSymbolAddress(&peh, g_ehi);   cudaGetSymbolAddress(&pel, g_elo);
    cudaGetSymbolAddress(&pemb, g_emb);
    typedef __nv_bfloat16 bf;

    // dynamic smem: 2 stages x (2*BM*40 + 2*32*(BN+8)) bf16  (R11-proven sizes)
    const int SM128 = 2 * (2 * 128 * 40 + 2 * 32 * 136) * 2;   // 75776
    const int SM64  = 2 * (2 * 64 * 40 + 2 * 32 * 72) * 2;     // 38912
    (void)cudaFuncSetAttribute((const void*)hgemm_cp<128, 128, 32, 64, 1, true>,
                               cudaFuncAttributeMaxDynamicSharedMemorySize, SM128);
    (void)cudaFuncSetAttribute((const void*)hgemm_cp<128, 128, 32, 64, 0, false>,
                               cudaFuncAttributeMaxDynamicSharedMemorySize, SM128);
    (void)cudaFuncSetAttribute((const void*)hgemm_cp<64, 64, 16, 32, 2, false>,
                               cudaFuncAttributeMaxDynamicSharedMemorySize, SM64);

    // launch 1: split x (+ init)
    split_x_init_kernel<<<NPTS * DIN / 1024, 256>>>(x);
    // launch 2: split all weights
    split_w_all_kernel<<<WTOT / 1024, 256>>>(W1, W2, W3, W4);

    // launch 3: h1 = tanh(data @ W1 + b1) -> split bf16 only
    {
        dim3 grid(HID / 128, NPTS / 128);
        hgemm_cp<128, 128, 32, 64, 1, true><<<grid, 256, SM128>>>(
            (bf*)pxh, (bf*)pxl, (bf*)p1h, (bf*)p1l, b1,
            nullptr, (bf*)ph1h, (bf*)ph1l, DIN, HID);
    }
    // launch 4: emb = h1 @ W2 + b2 -> fp32 + split
    {
        dim3 grid(EMBD / 64, NPTS / 64);
        hgemm_cp<64, 64, 16, 32, 2, false><<<grid, 256, SM64>>>(
            (bf*)ph1h, (bf*)ph1l, (bf*)p2h, (bf*)p2l, b2,
            (float*)pemb, (bf*)peh, (bf*)pel, HID, EMBD);
    }
    // launch 5: h2 = tanh(emb @ W3 + b3) -> split bf16 only
    {
        dim3 grid(HID / 128, NPTS / 128);
        hgemm_cp<128, 128, 32, 64, 1, true><<<grid, 256, SM128>>>(
            (bf*)peh, (bf*)pel, (bf*)p3h, (bf*)p3l, b3,
            nullptr, (bf*)ph2h, (bf*)ph2l, EMBD, HID);
    }
    // launch 6 (profiled by -s 5 -c 1): decoded = h2 @ W4 + b4 -> fp32 out
    {
        dim3 grid(DIN / 128, NPTS / 128);
        hgemm_cp<128, 128, 32, 64, 0, false><<<grid, 256, SM128>>>(
            (bf*)ph2h, (bf*)ph2l, (bf*)p4h, (bf*)p4l, b4,
            out, nullptr, nullptr, HID, DIN);
    }

    stats_kernel<<<NPTS / 256, 256>>>(x);
    offsets_kernel<<<1, 32>>>();
    scatter_kernel<<<NPTS / 256, 256>>>();
    pairwise_kernel<<<4096, 256>>>();
    finalize_kernel<<<1, 256>>>(out);
}

// round 15
// speedup vs baseline: 1.5608x; 1.5608x over previous
#include <cuda_runtime.h>
#include <cuda_bf16.h>
#include <cuda_pipeline.h>
#include <mma.h>
#include <math.h>
#include <stdint.h>

using namespace nvcuda;

#define NPTS 8192
#define DIN  512
#define HID  1024
#define EMBD 64
#define NEFF 2
#define NCONS 62   // EMBD - NEFF
#define NCLS 16
#define MARGIN 0.01f

// ---------------- scratch (static device globals; no allocation) ----------------
__device__ __nv_bfloat16 g_xhi[NPTS * DIN],  g_xlo[NPTS * DIN];
__device__ __nv_bfloat16 g_w1hi[DIN * HID],  g_w1lo[DIN * HID];
__device__ __nv_bfloat16 g_w2hi[HID * EMBD], g_w2lo[HID * EMBD];
__device__ __nv_bfloat16 g_w3hi[EMBD * HID], g_w3lo[EMBD * HID];
__device__ __nv_bfloat16 g_w4hi[HID * DIN],  g_w4lo[HID * DIN];
__device__ __nv_bfloat16 g_h1hi[NPTS * HID], g_h1lo[NPTS * HID];
__device__ __nv_bfloat16 g_h2hi[NPTS * HID], g_h2lo[NPTS * HID];
__device__ __nv_bfloat16 g_ehi[NPTS * EMBD], g_elo[NPTS * EMBD];
__device__ float g_emb[NPTS * EMBD];
__device__ float g_sq[NPTS];
__device__ int   g_lbl[NPTS];
__device__ int   g_cnt[NCLS];
__device__ int   g_off[NCLS + 1];
__device__ int   g_cur[NCLS];
__device__ int   g_perm[NPTS];
__device__ int   g_tileoff[NCLS + 1];
__device__ float g_msum[NCLS * NCONS];
__device__ float g_T[NCLS];
__device__ float g_cdiff;

__device__ __forceinline__ uint32_t pack_bf2(__nv_bfloat16 a, __nv_bfloat16 b) {
    __nv_bfloat162 t = __halves2bfloat162(a, b);
    return *reinterpret_cast<uint32_t*>(&t);
}

// ---------------- split x (+ fused init of per-launch accumulators) ----------------
__global__ void split_x_init_kernel(const float* __restrict__ x) {
    if (blockIdx.x == 0) {
        int t = threadIdx.x;
        for (int i = t; i < NCLS * NCONS; i += 256) g_msum[i] = 0.f;
        if (t < NCLS) { g_T[t] = 0.f; g_cnt[t] = 0; g_cur[t] = 0; }
        if (t == 0) g_cdiff = 0.f;
    }
    int q = blockIdx.x * 256 + threadIdx.x;       // quad index; NPTS*DIN/1024 blocks, exact
    int r = q / (DIN / 4), c = (q % (DIN / 4)) * 4;
    const float* xp = x + (long)r * (DIN + 1) + 1 + c;
    float v0 = xp[0], v1 = xp[1], v2 = xp[2], v3 = xp[3];
    __nv_bfloat16 h0 = __float2bfloat16(v0), h1 = __float2bfloat16(v1);
    __nv_bfloat16 h2 = __float2bfloat16(v2), h3 = __float2bfloat16(v3);
    uint2 uh, ul;
    uh.x = pack_bf2(h0, h1); uh.y = pack_bf2(h2, h3);
    ul.x = pack_bf2(__float2bfloat16(v0 - __bfloat162float(h0)),
                    __float2bfloat16(v1 - __bfloat162float(h1)));
    ul.y = pack_bf2(__float2bfloat16(v2 - __bfloat162float(h2)),
                    __float2bfloat16(v3 - __bfloat162float(h3)));
    *(uint2*)&g_xhi[q * 4] = uh;
    *(uint2*)&g_xlo[q * 4] = ul;
}

// ---------------- merged, vectorized weight split ----------------
#define W1N (DIN * HID)
#define W2N (HID * EMBD)
#define W3N (EMBD * HID)
#define W4N (HID * DIN)
#define WTOT (W1N + W2N + W3N + W4N)

__global__ void split_w_all_kernel(const float* __restrict__ W1, const float* __restrict__ W2,
                                   const float* __restrict__ W3, const float* __restrict__ W4) {
    int q = blockIdx.x * 256 + threadIdx.x;       // quad index; WTOT/1024 blocks, exact
    int idx = q * 4;
    const float* src;
    __nv_bfloat16 *hi, *lo;
    int off;
    if (idx < W1N)                    { src = W1; hi = g_w1hi; lo = g_w1lo; off = idx; }
    else if (idx < W1N + W2N)         { src = W2; hi = g_w2hi; lo = g_w2lo; off = idx - W1N; }
    else if (idx < W1N + W2N + W3N)   { src = W3; hi = g_w3hi; lo = g_w3lo; off = idx - W1N - W2N; }
    else                              { src = W4; hi = g_w4hi; lo = g_w4lo; off = idx - W1N - W2N - W3N; }
    float4 v = *(const float4*)&src[off];
    __nv_bfloat16 h0 = __float2bfloat16(v.x), h1 = __float2bfloat16(v.y);
    __nv_bfloat16 h2 = __float2bfloat16(v.z), h3 = __float2bfloat16(v.w);
    uint2 uh, ul;
    uh.x = pack_bf2(h0, h1); uh.y = pack_bf2(h2, h3);
    ul.x = pack_bf2(__float2bfloat16(v.x - __bfloat162float(h0)),
                    __float2bfloat16(v.y - __bfloat162float(h1)));
    ul.y = pack_bf2(__float2bfloat16(v.z - __bfloat162float(h2)),
                    __float2bfloat16(v.w - __bfloat162float(h3)));
    *(uint2*)&hi[off] = uh;
    *(uint2*)&lo[off] = ul;
}

// ================= WMMA bf16 split GEMM, cp.async 2-stage, interleaved term order =================
// OUTMODE: 0 = fp32 only, 1 = split bf16 only, 2 = both. STATS: fuse per-class stats (GEMM2 only).
template<int BM, int BN, int WM, int WN, int OUTMODE, bool DOTANH, bool STATS>
__global__ __launch_bounds__(256, 2)
void hgemm_cp(const __nv_bfloat16* __restrict__ Ahi_g, const __nv_bfloat16* __restrict__ Alo_g,
              const __nv_bfloat16* __restrict__ Bhi_g, const __nv_bfloat16* __restrict__ Blo_g,
              const float* __restrict__ bias,
              float* __restrict__ C, __nv_bfloat16* __restrict__ Chi,
              __nv_bfloat16* __restrict__ Clo, int K, int N,
              const float* __restrict__ xlab)
{
    constexpr int BK = 32, BKP = 40, BNP = BN + 8;
    constexpr int MW = BM / WM, NW = BN / WN;
    static_assert(MW * NW == 8, "8 warps");
    constexpr int MFRAG = WM / 16, NFRAG = WN / 16;
    constexpr int NP = (NFRAG >= 2) ? 2 : 1;       // nf pair width for term interleave
    constexpr int A_EL = BM * BKP;
    constexpr int B_EL = BK * BNP;
    constexpr int STAGE_EL = 2 * A_EL + 2 * B_EL;

    extern __shared__ __align__(16) unsigned char dsm[];
    __nv_bfloat16* sbase = (__nv_bfloat16*)dsm;
    float* stage_epi = (float*)dsm;                // overlays tiles (dead in epilogue)

    const int tid = threadIdx.x;
    const int wid = tid >> 5, lid = tid & 31;
    const int wm = wid % MW, wn = wid / MW;
    const int rowBase = blockIdx.y * BM;
    const int n0 = blockIdx.x * BN;

    auto AhiS = [&](int s) { return sbase + s * STAGE_EL; };
    auto AloS = [&](int s) { return sbase + s * STAGE_EL + A_EL; };
    auto BhiS = [&](int s) { return sbase + s * STAGE_EL + 2 * A_EL; };
    auto BloS = [&](int s) { return sbase + s * STAGE_EL + 2 * A_EL + B_EL; };

    auto load_stage = [&](int s, int ch) {
        const int k0 = ch * BK;
        __nv_bfloat16* ah = AhiS(s);
        __nv_bfloat16* al = AloS(s);
        __nv_bfloat16* bh = BhiS(s);
        __nv_bfloat16* bl = BloS(s);
        constexpr int AU = BM * BK / 8;
#pragma unroll
        for (int i = tid; i < AU; i += 256) {
            int r = i >> 2, c8 = (i & 3) << 3;
            long src = (long)(rowBase + r) * K + k0 + c8;
            int dst = r * BKP + c8;
            __pipeline_memcpy_async(&ah[dst], &Ahi_g[src], 16);
            __pipeline_memcpy_async(&al[dst], &Alo_g[src], 16);
        }
        constexpr int BU = BK * BN / 8;
        constexpr int BROW = BN / 8;
#pragma unroll
        for (int i = tid; i < BU; i += 256) {
            int r = i / BROW, c8 = (i % BROW) << 3;
            long src = (long)(k0 + r) * N + n0 + c8;
            int dst = r * BNP + c8;
            __pipeline_memcpy_async(&bh[dst], &Bhi_g[src], 16);
            __pipeline_memcpy_async(&bl[dst], &Blo_g[src], 16);
        }
        __pipeline_commit();
    };

    wmma::fragment<wmma::accumulator, 16, 16, 16, float> acc[MFRAG][NFRAG];
#pragma unroll
    for (int mf = 0; mf < MFRAG; mf++)
#pragma unroll
        for (int nf = 0; nf < NFRAG; nf++)
            wmma::fill_fragment(acc[mf][nf], 0.0f);

    const int nChunks = K / BK;
    load_stage(0, 0);

    for (int ch = 0; ch < nChunks; ch++) {
        const int buf = ch & 1;
        if (ch + 1 < nChunks) {
            load_stage(buf ^ 1, ch + 1);
            __pipeline_wait_prior(1);
        } else {
            __pipeline_wait_prior(0);
        }
        __syncthreads();

        const __nv_bfloat16* Ahi = AhiS(buf);
        const __nv_bfloat16* Alo = AloS(buf);
        const __nv_bfloat16* Bhi = BhiS(buf);
        const __nv_bfloat16* Blo = BloS(buf);

#pragma unroll
        for (int kf = 0; kf < BK / 16; kf++) {
            wmma::fragment<wmma::matrix_a, 16, 16, 16, __nv_bfloat16, wmma::row_major> ah[MFRAG], al[MFRAG];
#pragma unroll
            for (int mf = 0; mf < MFRAG; mf++) {
                wmma::load_matrix_sync(ah[mf], &Ahi[(wm * WM + mf * 16) * BKP + kf * 16], BKP);
                wmma::load_matrix_sync(al[mf], &Alo[(wm * WM + mf * 16) * BKP + kf * 16], BKP);
            }
            // interleaved term order: per nf-pair, issue all term-1 MMAs, then term-2, then term-3.
            // Per-accumulator accumulation order is unchanged (hh, lh, hl) -> bitwise-identical result,
            // but same-acc reuse distance grows from 1 to NP*MFRAG, breaking the HMMA RAW chain.
#pragma unroll
            for (int np = 0; np < NFRAG; np += NP) {
                wmma::fragment<wmma::matrix_b, 16, 16, 16, __nv_bfloat16, wmma::row_major> bh[NP], bl[NP];
#pragma unroll
                for (int j = 0; j < NP; j++) {
                    wmma::load_matrix_sync(bh[j], &Bhi[(kf * 16) * BNP + wn * WN + (np + j) * 16], BNP);
                    wmma::load_matrix_sync(bl[j], &Blo[(kf * 16) * BNP + wn * WN + (np + j) * 16], BNP);
                }
#pragma unroll
                for (int j = 0; j < NP; j++)
#pragma unroll
                    for (int mf = 0; mf < MFRAG; mf++)
                        wmma::mma_sync(acc[mf][np + j], ah[mf], bh[j], acc[mf][np + j]);
#pragma unroll
                for (int j = 0; j < NP; j++)
#pragma unroll
                    for (int mf = 0; mf < MFRAG; mf++)
                        wmma::mma_sync(acc[mf][np + j], al[mf], bh[j], acc[mf][np + j]);
#pragma unroll
                for (int j = 0; j < NP; j++)
#pragma unroll
                    for (int mf = 0; mf < MFRAG; mf++)
                        wmma::mma_sync(acc[mf][np + j], ah[mf], bl[j], acc[mf][np + j]);
            }
        }
        __syncthreads();
    }

    // ---- epilogue via per-warp smem staging ----
    float* wstage = stage_epi + wid * (16 * 20);
    float* embS = stage_epi + 8 * (16 * 20);       // [BM][68] fp32 (STATS only; fits in tile smem)
#pragma unroll
    for (int mf = 0; mf < MFRAG; mf++) {
#pragma unroll
        for (int nf = 0; nf < NFRAG; nf++) {
            wmma::store_matrix_sync(wstage, acc[mf][nf], 20, wmma::mem_row_major);
            __syncwarp();
            int r = lid >> 1, c0 = (lid & 1) << 3;
            int lrow = wm * WM + mf * 16 + r;
            long grow = rowBase + lrow;
            int lcol = wn * WN + nf * 16 + c0;
            int gcol = n0 + lcol;
            const float4* bp = (const float4*)&bias[gcol];
            float4 b0 = bp[0], b1 = bp[1];
            float v[8];
            v[0] = wstage[r * 20 + c0 + 0] + b0.x;
            v[1] = wstage[r * 20 + c0 + 1] + b0.y;
            v[2] = wstage[r * 20 + c0 + 2] + b0.z;
            v[3] = wstage[r * 20 + c0 + 3] + b0.w;
            v[4] = wstage[r * 20 + c0 + 4] + b1.x;
            v[5] = wstage[r * 20 + c0 + 5] + b1.y;
            v[6] = wstage[r * 20 + c0 + 6] + b1.z;
            v[7] = wstage[r * 20 + c0 + 7] + b1.w;
            if (DOTANH) {
#pragma unroll
                for (int j = 0; j < 8; j++) v[j] = tanhf(v[j]);
            }
            if (OUTMODE != 1) {
                float4* cp = (float4*)&C[grow * N + gcol];
                cp[0] = make_float4(v[0], v[1], v[2], v[3]);
                cp[1] = make_float4(v[4], v[5], v[6], v[7]);
            }
            if (STATS) {
#pragma unroll
                for (int j = 0; j < 8; j++) embS[lrow * 68 + lcol + j] = v[j];
            }
            if (OUTMODE >= 1) {
                __nv_bfloat16 h[8];
                uint4 uh, ul;
#pragma unroll
                for (int j = 0; j < 8; j++) h[j] = __float2bfloat16(v[j]);
                uh.x = pack_bf2(h[0], h[1]); uh.y = pack_bf2(h[2], h[3]);
                uh.z = pack_bf2(h[4], h[5]); uh.w = pack_bf2(h[6], h[7]);
                __nv_bfloat16 l[8];
#pragma unroll
                for (int j = 0; j < 8; j++)
                    l[j] = __float2bfloat16(v[j] - __bfloat162float(h[j]));
                ul.x = pack_bf2(l[0], l[1]); ul.y = pack_bf2(l[2], l[3]);
                ul.z = pack_bf2(l[4], l[5]); ul.w = pack_bf2(l[6], l[7]);
                *(uint4*)&Chi[grow * N + gcol] = uh;
                *(uint4*)&Clo[grow * N + gcol] = ul;
            }
            __syncwarp();
        }
    }

    if (STATS) {
        __shared__ float s_cls[NCLS * NCONS];
        __shared__ float s_T[NCLS];
        __shared__ int   s_C[NCLS];
        for (int i = tid; i < NCLS * NCONS; i += 256) s_cls[i] = 0.f;
        if (tid < NCLS) { s_T[tid] = 0.f; s_C[tid] = 0; }
        __syncthreads();
        if (tid < BM) {
            long gi = rowBase + tid;
            int l = (int)xlab[gi * (DIN + 1)];
            float sq = 0.f;
#pragma unroll
            for (int d = 0; d < NCONS; d++) {
                float v = embS[tid * 68 + NEFF + d];
                sq += v * v;
                atomicAdd(&s_cls[l * NCONS + d], v);
            }
            g_sq[gi] = sq;
            g_lbl[gi] = l;
            atomicAdd(&s_T[l], sq);
            atomicAdd(&s_C[l], 1);
        }
        __syncthreads();
        for (int i = tid; i < NCLS * NCONS; i += 256)
            if (s_cls[i] != 0.f) atomicAdd(&g_msum[i], s_cls[i]);
        if (tid < NCLS && s_C[tid] > 0) {
            atomicAdd(&g_T[tid], s_T[tid]);
            atomicAdd(&g_cnt[tid], s_C[tid]);
        }
    }
}

// ---------------- counting-sort offsets + tile offsets ----------------
__global__ void offsets_kernel() {
    if (threadIdx.x == 0 && blockIdx.x == 0) {
        int acc = 0, tacc = 0;
        for (int k = 0; k < NCLS; k++) {
            g_off[k] = acc; acc += g_cnt[k];
            g_cur[k] = 0;
            int t = (g_cnt[k] + 31) >> 5;
            g_tileoff[k] = tacc; tacc += t * t;
        }
        g_off[NCLS] = acc;
        g_tileoff[NCLS] = tacc;
    }
}

__global__ void scatter_kernel() {
    int i = blockIdx.x * blockDim.x + threadIdx.x;
    int l = g_lbl[i];
    int pos = g_off[l] + atomicAdd(&g_cur[l], 1);
    g_perm[pos] = i;
}

// ---------------- same-class pairwise C_diff (persistent tile loop) ----------------
__global__ __launch_bounds__(256)
void pairwise_kernel() {
    __shared__ float Ci[32][NCONS + 1];
    __shared__ float Cj[32][NCONS + 1];
    __shared__ float sqi[32], sqj[32];
    __shared__ float red[256];

    int tid = threadIdx.x;
    int total = g_tileoff[NCLS];
    float accT = 0.f;

    for (int w = blockIdx.x; w < total; w += gridDim.x) {
        int k = 0;
        while (g_tileoff[k + 1] <= w) k++;
        int n = g_cnt[k];
        int tpd = (n + 31) >> 5;
        int local = w - g_tileoff[k];
        int ti = local / tpd, tj = local % tpd;
        int base = g_off[k];
        int ni = min(32, n - ti * 32);
        int nj = min(32, n - tj * 32);

        __syncthreads();
        for (int idx = tid; idx < 32 * NCONS; idx += blockDim.x) {
            int r = idx / NCONS, d = idx % NCONS;
            int a = ti * 32 + r;
            if (a < n) {
                int gi = g_perm[base + a];
                Ci[r][d] = g_emb[(long)gi * EMBD + NEFF + d];
                if (d == 0) sqi[r] = g_sq[gi];
            }
            int b = tj * 32 + r;
            if (b < n) {
                int gj = g_perm[base + b];
                Cj[r][d] = g_emb[(long)gj * EMBD + NEFF + d];
                if (d == 0) sqj[r] = g_sq[gj];
            }
        }
        __syncthreads();

        int b = tid & 31;
        int a0 = tid >> 5;
        if (b < nj) {
            float dot0 = 0.f, dot1 = 0.f, dot2 = 0.f, dot3 = 0.f;
#pragma unroll
            for (int d = 0; d < NCONS; d++) {
                float cj = Cj[b][d];
                dot0 += Ci[a0][d] * cj;
                dot1 += Ci[a0 + 8][d] * cj;
                dot2 += Ci[a0 + 16][d] * cj;
                dot3 += Ci[a0 + 24][d] * cj;
            }
            float sj = sqj[b];
            float dots[4] = {dot0, dot1, dot2, dot3};
#pragma unroll
            for (int m = 0; m < 4; m++) {
                int a = a0 + m * 8;
                if (a < ni) {
                    float D = fmaxf(sqi[a] + sj - 2.f * dots[m], 0.f) * (1.f / NCONS);
                    float t = MARGIN - D;
                    if (t > 0.f) accT += t;
                }
            }
        }
    }

    red[tid] = accT;
    __syncthreads();
    for (int s = 128; s > 0; s >>= 1) {
        if (tid < s) red[tid] += red[tid + s];
        __syncthreads();
    }
    if (tid == 0 && red[0] != 0.f) atomicAdd(&g_cdiff, red[0]);
}

// ---------------- finalize: parallel closed-form C_sim, normalize C_diff ----------------
__global__ void finalize_kernel(float* __restrict__ out) {
    __shared__ float Msh[NCONS];
    __shared__ float s_summ2, s_sumTw, s_MM;
    __shared__ unsigned long long s_n2;
    int tid = threadIdx.x;
    if (tid < NCONS) Msh[tid] = 0.f;
    if (tid == 0) { s_summ2 = 0.f; s_sumTw = 0.f; s_MM = 0.f; s_n2 = 0ull; }
    __syncthreads();

    float p2 = 0.f;
    for (int i = tid; i < NCLS * NCONS; i += blockDim.x) {
        float v = g_msum[i];
        p2 += v * v;
        atomicAdd(&Msh[i % NCONS], v);
    }
    if (p2 != 0.f) atomicAdd(&s_summ2, p2);
    if (tid < NCLS) {
        int n = g_cnt[tid];
        atomicAdd(&s_n2, (unsigned long long)n * (unsigned long long)n);
        atomicAdd(&s_sumTw, g_T[tid] * (float)(NPTS - n));
    }
    __syncthreads();
    if (tid < NCONS) atomicAdd(&s_MM, Msh[tid] * Msh[tid]);
    __syncthreads();

    if (tid == 0) {
        double ndiff = (double)NPTS * (double)NPTS - (double)s_n2;
        float raw = 2.f * s_sumTw - 2.f * (s_MM - s_summ2);
        float csim = raw * (1.f / NCONS) / (float)(ndiff + 1.0);
        float cdiff = g_cdiff / (float)((double)NPTS * (double)NPTS - ndiff + 1.0);
        out[(long)NPTS * DIN]     = csim;
        out[(long)NPTS * DIN + 1] = cdiff;
    }
}

// ---------------- launch ----------------
extern "C" void kernel_launch(void* const* d_in, const int* in_sizes, int n_in,
                              void* d_out, int out_size) {
    const float* x  = (const float*)d_in[0];
    const float* W1 = (const float*)d_in[1];
    const float* b1 = (const float*)d_in[2];
    const float* W2 = (const float*)d_in[3];
    const float* b2 = (const float*)d_in[4];
    const float* W3 = (const float*)d_in[5];
    const float* b3 = (const float*)d_in[6];
    const float* W4 = (const float*)d_in[7];
    const float* b4 = (const float*)d_in[8];
    float* out = (float*)d_out;

    void *pxh, *pxl, *p1h, *p1l, *p2h, *p2l, *p3h, *p3l, *p4h, *p4l;
    void *ph1h, *ph1l, *ph2h, *ph2l, *peh, *pel, *pemb;
    cudaGetSymbolAddress(&pxh, g_xhi);   cudaGetSymbolAddress(&pxl, g_xlo);
    cudaGetSymbolAddress(&p1h, g_w1hi);  cudaGetSymbolAddress(&p1l, g_w1lo);
    cudaGetSymbolAddress(&p2h, g_w2hi);  cudaGetSymbolAddress(&p2l, g_w2lo);
    cudaGetSymbolAddress(&p3h, g_w3hi);  cudaGetSymbolAddress(&p3l, g_w3lo);
    cudaGetSymbolAddress(&p4h, g_w4hi);  cudaGetSymbolAddress(&p4l, g_w4lo);
    cudaGetSymbolAddress(&ph1h, g_h1hi); cudaGetSymbolAddress(&ph1l, g_h1lo);
    cudaGetSymbolAddress(&ph2h, g_h2hi); cudaGetSymbolAddress(&ph2l, g_h2lo);
    cudaGetSymbolAddress(&peh, g_ehi);   cudaGetSymbolAddress(&pel, g_elo);
    cudaGetSymbolAddress(&pemb, g_emb);
    typedef __nv_bfloat16 bf;

    const int SM128 = 2 * (2 * 128 * 40 + 2 * 32 * 136) * 2;   // 75776
    const int SM64  = 2 * (2 * 64 * 40 + 2 * 32 * 72) * 2;     // 38912
    (void)cudaFuncSetAttribute((const void*)hgemm_cp<128, 128, 32, 64, 1, true, false>,
                               cudaFuncAttributeMaxDynamicSharedMemorySize, SM128);
    (void)cudaFuncSetAttribute((const void*)hgemm_cp<128, 128, 32, 64, 0, false, false>,
                               cudaFuncAttributeMaxDynamicSharedMemorySize, SM128);
    (void)cudaFuncSetAttribute((const void*)hgemm_cp<64, 64, 16, 32, 2, false, true>,
                               cudaFuncAttributeMaxDynamicSharedMemorySize, SM64);

    // launch 1: split x (+ init)
    split_x_init_kernel<<<NPTS * DIN / 1024, 256>>>(x);
    // launch 2: split all weights
    split_w_all_kernel<<<WTOT / 1024, 256>>>(W1, W2, W3, W4);

    // launch 3: h1 = tanh(data @ W1 + b1) -> split bf16 only
    {
        dim3 grid(HID / 128, NPTS / 128);
        hgemm_cp<128, 128, 32, 64, 1, true, false><<<grid, 256, SM128>>>(
            (bf*)pxh, (bf*)pxl, (bf*)p1h, (bf*)p1l, b1,
            nullptr, (bf*)ph1h, (bf*)ph1l, DIN, HID, nullptr);
    }
    // launch 4: emb = h1 @ W2 + b2 -> fp32 + split + fused stats
    {
        dim3 grid(EMBD / 64, NPTS / 64);
        hgemm_cp<64, 64, 16, 32, 2, false, true><<<grid, 256, SM64>>>(
            (bf*)ph1h, (bf*)ph1l, (bf*)p2h, (bf*)p2l, b2,
            (float*)pemb, (bf*)peh, (bf*)pel, HID, EMBD, x);
    }
    // launch 5: h2 = tanh(emb @ W3 + b3) -> split bf16 only
    {
        dim3 grid(HID / 128, NPTS / 128);
        hgemm_cp<128, 128, 32, 64, 1, true, false><<<grid, 256, SM128>>>(
            (bf*)peh, (bf*)pel, (bf*)p3h, (bf*)p3l, b3,
            nullptr, (bf*)ph2h, (bf*)ph2l, EMBD, HID, nullptr);
    }
    // launch 6: decoded = h2 @ W4 + b4 -> fp32 out
    {
        dim3 grid(DIN / 128, NPTS / 128);
        hgemm_cp<128, 128, 32, 64, 0, false, false><<<grid, 256, SM128>>>(
            (bf*)ph2h, (bf*)ph2l, (bf*)p4h, (bf*)p4l, b4,
            out, nullptr, nullptr, HID, DIN, nullptr);
    }

    offsets_kernel<<<1, 32>>>();
    scatter_kernel<<<NPTS / 256, 256>>>();
    pairwise_kernel<<<4096, 256>>>();
    finalize_kernel<<<1, 256>>>(out);
}